// round 4
// baseline (speedup 1.0000x reference)
#include <cuda_runtime.h>
#include <math.h>

// Problem constants
#define BN 4
#define KN 16
#define HW (512*512)
#define HW4 (HW/4)
#define LOG_2PI 1.8378770664093453f
#define LOG2E 1.4426950408889634f

// Reduction config
#define KG 8            // k-groups
#define KPT 2           // k per thread (KG*KPT == KN)
#define CHUNKS 32       // pixel chunks per (b, kgroup)
#define RTHREADS 256
#define RITERS (HW4 / (CHUNKS * RTHREADS))   // = 8, exact
#define NSTAT 10

// Deterministic scratch (no allocations allowed)
__device__ float g_part[BN * KG * CHUNKS * KPT * NSTAT];
__device__ float g_params[BN * KN * NSTAT];

typedef unsigned long long u64;

__device__ __forceinline__ u64 pack2(float lo, float hi) {
    u64 r; asm("mov.b64 %0,{%1,%2};" : "=l"(r) : "f"(lo), "f"(hi)); return r;
}
__device__ __forceinline__ void unpack2(u64 v, float& lo, float& hi) {
    asm("mov.b64 {%0,%1},%2;" : "=f"(lo), "=f"(hi) : "l"(v));
}
__device__ __forceinline__ u64 fma2(u64 a, u64 b, u64 c) {
    u64 d; asm("fma.rn.f32x2 %0,%1,%2,%3;" : "=l"(d) : "l"(a), "l"(b), "l"(c)); return d;
}
__device__ __forceinline__ u64 mul2(u64 a, u64 b) {
    u64 d; asm("mul.rn.f32x2 %0,%1,%2;" : "=l"(d) : "l"(a), "l"(b)); return d;
}
__device__ __forceinline__ u64 add2(u64 a, u64 b) {
    u64 d; asm("add.rn.f32x2 %0,%1,%2;" : "=l"(d) : "l"(a), "l"(b)); return d;
}
__device__ __forceinline__ float ex2(float x) {
    float y; asm("ex2.approx.f32 %0,%1;" : "=f"(y) : "f"(x)); return y;
}
__device__ __forceinline__ u64 exp2_2(u64 t) {
    float lo, hi; unpack2(t, lo, hi);
    return pack2(ex2(lo), ex2(hi));
}

// ---------------------------------------------------------------------------
// Pass A: per-(b,k) partial sufficient statistics, float4 loads, scalar FMA.
// grid = (CHUNKS, KG, BN), block = RTHREADS. No atomics -> deterministic.
// ---------------------------------------------------------------------------
__global__ __launch_bounds__(RTHREADS, 5)
void gmm_reduce_kernel(const float* __restrict__ P, const float* __restrict__ I) {
    const int b = blockIdx.z, kg = blockIdx.y, chunk = blockIdx.x;
    const int tid = threadIdx.x;

    const float4* __restrict__ I0 = (const float4*)(I + (size_t)(b * 3 + 0) * HW);
    const float4* __restrict__ I1 = (const float4*)(I + (size_t)(b * 3 + 1) * HW);
    const float4* __restrict__ I2 = (const float4*)(I + (size_t)(b * 3 + 2) * HW);
    const float4* __restrict__ Pb = (const float4*)(P + ((size_t)b * KN + (size_t)kg * KPT) * HW);

    float acc[KPT][NSTAT];
#pragma unroll
    for (int j = 0; j < KPT; j++)
#pragma unroll
        for (int s = 0; s < NSTAT; s++) acc[j][s] = 0.0f;

    const int stride = CHUNKS * RTHREADS;
    int p = chunk * RTHREADS + tid;
#pragma unroll 2
    for (int it = 0; it < RITERS; it++, p += stride) {
        const float4 a0 = I0[p];
        const float4 a1 = I1[p];
        const float4 a2 = I2[p];
        float4 w[KPT];
#pragma unroll
        for (int j = 0; j < KPT; j++)
            w[j] = __ldcs(&Pb[(size_t)j * HW4 + p]);

        const float x0[4] = {a0.x, a0.y, a0.z, a0.w};
        const float x1[4] = {a1.x, a1.y, a1.z, a1.w};
        const float x2[4] = {a2.x, a2.y, a2.z, a2.w};
#pragma unroll
        for (int l = 0; l < 4; l++) {
            const float v0 = x0[l], v1 = x1[l], v2 = x2[l];
            const float p00 = v0 * v0, p01 = v0 * v1, p02 = v0 * v2;
            const float p11 = v1 * v1, p12 = v1 * v2, p22 = v2 * v2;
#pragma unroll
            for (int j = 0; j < KPT; j++) {
                const float wl = (l == 0) ? w[j].x : (l == 1) ? w[j].y : (l == 2) ? w[j].z : w[j].w;
                acc[j][0] += wl;
                acc[j][1] = fmaf(wl, v0, acc[j][1]);
                acc[j][2] = fmaf(wl, v1, acc[j][2]);
                acc[j][3] = fmaf(wl, v2, acc[j][3]);
                acc[j][4] = fmaf(wl, p00, acc[j][4]);
                acc[j][5] = fmaf(wl, p01, acc[j][5]);
                acc[j][6] = fmaf(wl, p02, acc[j][6]);
                acc[j][7] = fmaf(wl, p11, acc[j][7]);
                acc[j][8] = fmaf(wl, p12, acc[j][8]);
                acc[j][9] = fmaf(wl, p22, acc[j][9]);
            }
        }
    }

    // warp reduce all KPT*NSTAT accumulators
#pragma unroll
    for (int j = 0; j < KPT; j++)
#pragma unroll
        for (int s = 0; s < NSTAT; s++)
#pragma unroll
            for (int off = 16; off > 0; off >>= 1)
                acc[j][s] += __shfl_down_sync(0xffffffffu, acc[j][s], off);

    __shared__ float sh[RTHREADS / 32][KPT * NSTAT];
    const int warp = tid >> 5, lane = tid & 31;
    if (lane == 0) {
#pragma unroll
        for (int j = 0; j < KPT; j++)
#pragma unroll
            for (int s = 0; s < NSTAT; s++)
                sh[warp][j * NSTAT + s] = acc[j][s];
    }
    __syncthreads();

    if (tid < KPT * NSTAT) {
        float v = 0.0f;
#pragma unroll
        for (int w = 0; w < RTHREADS / 32; w++) v += sh[w][tid];
        g_part[((size_t)(b * KG + kg) * CHUNKS + chunk) * (KPT * NSTAT) + tid] = v;
    }
}

// ---------------------------------------------------------------------------
// Pass B: finalize per-(b,k) params in log2-domain affine form.
// params per (b,k): C0, G0,G1,G2, Hn00,Hn11,Hn22, Hn01,Hn02,Hn12
//   logit2(x) = C0 + G.x + Hn.(x products); q = exp2(logit2)
// ---------------------------------------------------------------------------
__global__ void gmm_params_kernel() {
    const int t = threadIdx.x;
    if (t >= BN * KN) return;
    const int b = t / KN, k = t % KN;
    const int kg = k / KPT, j = k % KPT;

    float s[NSTAT];
#pragma unroll
    for (int i = 0; i < NSTAT; i++) s[i] = 0.0f;
    for (int c = 0; c < CHUNKS; c++) {
        const float* p = &g_part[((size_t)(b * KG + kg) * CHUNKS + c) * (KPT * NSTAT) + j * NSTAT];
#pragma unroll
        for (int i = 0; i < NSTAT; i++) s[i] += p[i];
    }

    const float SP = s[0];
    const float rd = 1.0f / (1e-5f + SP);
    const float mu0 = s[1] * rd, mu1 = s[2] * rd, mu2 = s[3] * rd;

    const float c00 = (s[4] - 2.0f * mu0 * s[1] + SP * mu0 * mu0) * rd + 1e-3f;
    const float c01 = (s[5] - mu0 * s[2] - mu1 * s[1] + SP * mu0 * mu1) * rd;
    const float c02 = (s[6] - mu0 * s[3] - mu2 * s[1] + SP * mu0 * mu2) * rd;
    const float c11 = (s[7] - 2.0f * mu1 * s[2] + SP * mu1 * mu1) * rd + 1e-3f;
    const float c12 = (s[8] - mu1 * s[3] - mu2 * s[2] + SP * mu1 * mu2) * rd;
    const float c22 = (s[9] - 2.0f * mu2 * s[3] + SP * mu2 * mu2) * rd + 1e-3f;

    const float m00 = c11 * c22 - c12 * c12;
    const float m01 = c02 * c12 - c01 * c22;
    const float m02 = c01 * c12 - c02 * c11;
    const float det = c00 * m00 + c01 * m01 + c02 * m02;
    const float inv = 1.0f / det;

    const float i00 = m00 * inv;
    const float i01 = m01 * inv;
    const float i02 = m02 * inv;
    const float i11 = (c00 * c22 - c02 * c02) * inv;
    const float i12 = (c01 * c02 - c00 * c12) * inv;
    const float i22 = (c00 * c11 - c01 * c01) * inv;

    const float alpha = SP * (1.0f / (float)HW);
    const float logcoef = logf(alpha) - 0.5f * (3.0f * LOG_2PI + logf(det));

    // affine expansion: quad(x-mu) = Pq(x) - g.x + Pq(mu)
    const float g0 = i00 * mu0 + i01 * mu1 + i02 * mu2;
    const float g1 = i01 * mu0 + i11 * mu1 + i12 * mu2;
    const float g2 = i02 * mu0 + i12 * mu1 + i22 * mu2;
    const float Pmu = 0.5f * (i00 * mu0 * mu0 + i11 * mu1 * mu1 + i22 * mu2 * mu2)
                    + i01 * mu0 * mu1 + i02 * mu0 * mu2 + i12 * mu1 * mu2;

    float* out = &g_params[(size_t)(b * KN + k) * NSTAT];
    out[0] = (logcoef - Pmu) * LOG2E;
    out[1] = g0 * LOG2E;
    out[2] = g1 * LOG2E;
    out[3] = g2 * LOG2E;
    out[4] = -0.5f * i00 * LOG2E;
    out[5] = -0.5f * i11 * LOG2E;
    out[6] = -0.5f * i22 * LOG2E;
    out[7] = -i01 * LOG2E;
    out[8] = -i02 * LOG2E;
    out[9] = -i12 * LOG2E;
}

// ---------------------------------------------------------------------------
// Pass C: E-step, 4 pixels per thread, f32x2 math, two-sweep recompute
// (no persistent q[] array -> low register pressure).
// grid = (HW4/256, BN), block = 256
// ---------------------------------------------------------------------------
__device__ __forceinline__ u64 class_logit2(const u64* __restrict__ pr,
                                            u64 X0, u64 X1, u64 X2,
                                            u64 XX00, u64 XX01, u64 XX02,
                                            u64 XX11, u64 XX12, u64 XX22) {
    u64 t = fma2(pr[1], X0, pr[0]);
    t = fma2(pr[2], X1, t);
    t = fma2(pr[3], X2, t);
    t = fma2(pr[4], XX00, t);
    t = fma2(pr[5], XX11, t);
    t = fma2(pr[6], XX22, t);
    t = fma2(pr[7], XX01, t);
    t = fma2(pr[8], XX02, t);
    t = fma2(pr[9], XX12, t);
    return t;
}

__global__ __launch_bounds__(256)
void gmm_estep_kernel(const float* __restrict__ I, float* __restrict__ out) {
    const int b = blockIdx.y;
    const int p = blockIdx.x * blockDim.x + threadIdx.x;

    __shared__ u64 spd[KN * NSTAT];   // params duplicated into both f32x2 lanes
    if (threadIdx.x < KN * NSTAT) {
        const float v = g_params[(size_t)b * KN * NSTAT + threadIdx.x];
        spd[threadIdx.x] = pack2(v, v);
    }
    __syncthreads();

    const float4 a0 = ((const float4*)(I + (size_t)(b * 3 + 0) * HW))[p];
    const float4 a1 = ((const float4*)(I + (size_t)(b * 3 + 1) * HW))[p];
    const float4 a2 = ((const float4*)(I + (size_t)(b * 3 + 2) * HW))[p];

    u64 X0[2], X1[2], X2[2], XX00[2], XX01[2], XX02[2], XX11[2], XX12[2], XX22[2];
#pragma unroll
    for (int pi = 0; pi < 2; pi++) {
        X0[pi] = pi ? pack2(a0.z, a0.w) : pack2(a0.x, a0.y);
        X1[pi] = pi ? pack2(a1.z, a1.w) : pack2(a1.x, a1.y);
        X2[pi] = pi ? pack2(a2.z, a2.w) : pack2(a2.x, a2.y);
        XX00[pi] = mul2(X0[pi], X0[pi]);
        XX01[pi] = mul2(X0[pi], X1[pi]);
        XX02[pi] = mul2(X0[pi], X2[pi]);
        XX11[pi] = mul2(X1[pi], X1[pi]);
        XX12[pi] = mul2(X1[pi], X2[pi]);
        XX22[pi] = mul2(X2[pi], X2[pi]);
    }

    // sweep 1: denominator only
    u64 sum2[2] = {0ull, 0ull};
#pragma unroll
    for (int k = 0; k < KN; k++) {
        const u64* pr = &spd[k * NSTAT];
#pragma unroll
        for (int pi = 0; pi < 2; pi++) {
            const u64 t = class_logit2(pr, X0[pi], X1[pi], X2[pi],
                                       XX00[pi], XX01[pi], XX02[pi],
                                       XX11[pi], XX12[pi], XX22[pi]);
            sum2[pi] = add2(sum2[pi], exp2_2(t));
        }
    }

    float s0, s1, s2, s3;
    unpack2(sum2[0], s0, s1);
    unpack2(sum2[1], s2, s3);
    const u64 R[2] = { pack2(1.0f / (1e-5f + s0), 1.0f / (1e-5f + s1)),
                       pack2(1.0f / (1e-5f + s2), 1.0f / (1e-5f + s3)) };

    // sweep 2: recompute, normalize, store
    float4* __restrict__ o4 = (float4*)(out + (size_t)b * KN * HW);
#pragma unroll
    for (int k = 0; k < KN; k++) {
        const u64* pr = &spd[k * NSTAT];
        u64 v01, v23;
        {
            const u64 t = class_logit2(pr, X0[0], X1[0], X2[0],
                                       XX00[0], XX01[0], XX02[0],
                                       XX11[0], XX12[0], XX22[0]);
            v01 = mul2(exp2_2(t), R[0]);
        }
        {
            const u64 t = class_logit2(pr, X0[1], X1[1], X2[1],
                                       XX00[1], XX01[1], XX02[1],
                                       XX11[1], XX12[1], XX22[1]);
            v23 = mul2(exp2_2(t), R[1]);
        }
        float4 v;
        unpack2(v01, v.x, v.y);
        unpack2(v23, v.z, v.w);
        __stcs(&o4[(size_t)k * HW4 + p], v);
    }
}

extern "C" void kernel_launch(void* const* d_in, const int* in_sizes, int n_in,
                              void* d_out, int out_size) {
    const float* Pij = (const float*)d_in[0];
    const float* I   = (const float*)d_in[1];
    float* out = (float*)d_out;

    dim3 gA(CHUNKS, KG, BN);
    gmm_reduce_kernel<<<gA, RTHREADS>>>(Pij, I);
    gmm_params_kernel<<<1, 64>>>();
    dim3 gC(HW4 / 256, BN);
    gmm_estep_kernel<<<gC, 256>>>(I, out);
}

// round 5
// speedup vs baseline: 1.1768x; 1.1768x over previous
#include <cuda_runtime.h>
#include <math.h>

// Problem constants
#define BN 4
#define KN 16
#define HW (512*512)
#define HW4 (HW/4)
#define HW2 (HW/2)
#define LOG_2PI 1.8378770664093453f
#define LOG2E 1.4426950408889634f

// Reduction config
#define KG 8            // k-groups
#define KPT 2           // k per thread (KG*KPT == KN)
#define CHUNKS 32       // pixel chunks per (b, kgroup)
#define RTHREADS 256
#define RITERS (HW4 / (CHUNKS * RTHREADS))   // = 8, exact
#define NSTAT 10

// Deterministic scratch (no allocations allowed)
__device__ float g_part[BN * KG * CHUNKS * KPT * NSTAT];
__device__ float g_params[BN * KN * NSTAT];

typedef unsigned long long u64;

__device__ __forceinline__ u64 pack2(float lo, float hi) {
    u64 r; asm("mov.b64 %0,{%1,%2};" : "=l"(r) : "f"(lo), "f"(hi)); return r;
}
__device__ __forceinline__ void unpack2(u64 v, float& lo, float& hi) {
    asm("mov.b64 {%0,%1},%2;" : "=f"(lo), "=f"(hi) : "l"(v));
}
__device__ __forceinline__ u64 fma2(u64 a, u64 b, u64 c) {
    u64 d; asm("fma.rn.f32x2 %0,%1,%2,%3;" : "=l"(d) : "l"(a), "l"(b), "l"(c)); return d;
}
__device__ __forceinline__ u64 mul2(u64 a, u64 b) {
    u64 d; asm("mul.rn.f32x2 %0,%1,%2;" : "=l"(d) : "l"(a), "l"(b)); return d;
}
__device__ __forceinline__ u64 add2(u64 a, u64 b) {
    u64 d; asm("add.rn.f32x2 %0,%1,%2;" : "=l"(d) : "l"(a), "l"(b)); return d;
}
__device__ __forceinline__ float ex2(float x) {
    float y; asm("ex2.approx.f32 %0,%1;" : "=f"(y) : "f"(x)); return y;
}
__device__ __forceinline__ u64 exp2_2(u64 t) {
    float lo, hi; unpack2(t, lo, hi);
    return pack2(ex2(lo), ex2(hi));
}

// ---------------------------------------------------------------------------
// Pass A: per-(b,k) partial sufficient statistics, float4 loads, scalar FMA.
// grid = (CHUNKS, KG, BN), block = RTHREADS. No atomics -> deterministic.
// (Exact R2 configuration: natural 64 regs, no forced occupancy cap.)
// ---------------------------------------------------------------------------
__global__ __launch_bounds__(RTHREADS)
void gmm_reduce_kernel(const float* __restrict__ P, const float* __restrict__ I) {
    const int b = blockIdx.z, kg = blockIdx.y, chunk = blockIdx.x;
    const int tid = threadIdx.x;

    const float4* __restrict__ I0 = (const float4*)(I + (size_t)(b * 3 + 0) * HW);
    const float4* __restrict__ I1 = (const float4*)(I + (size_t)(b * 3 + 1) * HW);
    const float4* __restrict__ I2 = (const float4*)(I + (size_t)(b * 3 + 2) * HW);
    const float4* __restrict__ Pb = (const float4*)(P + ((size_t)b * KN + (size_t)kg * KPT) * HW);

    float acc[KPT][NSTAT];
#pragma unroll
    for (int j = 0; j < KPT; j++)
#pragma unroll
        for (int s = 0; s < NSTAT; s++) acc[j][s] = 0.0f;

    const int stride = CHUNKS * RTHREADS;
    int p = chunk * RTHREADS + tid;
#pragma unroll 2
    for (int it = 0; it < RITERS; it++, p += stride) {
        const float4 a0 = I0[p];
        const float4 a1 = I1[p];
        const float4 a2 = I2[p];
        float4 w[KPT];
#pragma unroll
        for (int j = 0; j < KPT; j++)
            w[j] = __ldcs(&Pb[(size_t)j * HW4 + p]);

        const float x0[4] = {a0.x, a0.y, a0.z, a0.w};
        const float x1[4] = {a1.x, a1.y, a1.z, a1.w};
        const float x2[4] = {a2.x, a2.y, a2.z, a2.w};
#pragma unroll
        for (int l = 0; l < 4; l++) {
            const float v0 = x0[l], v1 = x1[l], v2 = x2[l];
            const float p00 = v0 * v0, p01 = v0 * v1, p02 = v0 * v2;
            const float p11 = v1 * v1, p12 = v1 * v2, p22 = v2 * v2;
#pragma unroll
            for (int j = 0; j < KPT; j++) {
                const float wl = (l == 0) ? w[j].x : (l == 1) ? w[j].y : (l == 2) ? w[j].z : w[j].w;
                acc[j][0] += wl;
                acc[j][1] = fmaf(wl, v0, acc[j][1]);
                acc[j][2] = fmaf(wl, v1, acc[j][2]);
                acc[j][3] = fmaf(wl, v2, acc[j][3]);
                acc[j][4] = fmaf(wl, p00, acc[j][4]);
                acc[j][5] = fmaf(wl, p01, acc[j][5]);
                acc[j][6] = fmaf(wl, p02, acc[j][6]);
                acc[j][7] = fmaf(wl, p11, acc[j][7]);
                acc[j][8] = fmaf(wl, p12, acc[j][8]);
                acc[j][9] = fmaf(wl, p22, acc[j][9]);
            }
        }
    }

    // warp reduce all KPT*NSTAT accumulators
#pragma unroll
    for (int j = 0; j < KPT; j++)
#pragma unroll
        for (int s = 0; s < NSTAT; s++)
#pragma unroll
            for (int off = 16; off > 0; off >>= 1)
                acc[j][s] += __shfl_down_sync(0xffffffffu, acc[j][s], off);

    __shared__ float sh[RTHREADS / 32][KPT * NSTAT];
    const int warp = tid >> 5, lane = tid & 31;
    if (lane == 0) {
#pragma unroll
        for (int j = 0; j < KPT; j++)
#pragma unroll
            for (int s = 0; s < NSTAT; s++)
                sh[warp][j * NSTAT + s] = acc[j][s];
    }
    __syncthreads();

    if (tid < KPT * NSTAT) {
        float v = 0.0f;
#pragma unroll
        for (int w = 0; w < RTHREADS / 32; w++) v += sh[w][tid];
        g_part[((size_t)(b * KG + kg) * CHUNKS + chunk) * (KPT * NSTAT) + tid] = v;
    }
}

// ---------------------------------------------------------------------------
// Pass B: finalize per-(b,k) params in log2-domain affine form.
// params per (b,k): C0, G0,G1,G2, Hn00,Hn11,Hn22, Hn01,Hn02,Hn12
//   logit2(x) = C0 + G.x + Hn.(x products); q = exp2(logit2)
// ---------------------------------------------------------------------------
__global__ void gmm_params_kernel() {
    const int t = threadIdx.x;
    if (t >= BN * KN) return;
    const int b = t / KN, k = t % KN;
    const int kg = k / KPT, j = k % KPT;

    float s[NSTAT];
#pragma unroll
    for (int i = 0; i < NSTAT; i++) s[i] = 0.0f;
    for (int c = 0; c < CHUNKS; c++) {
        const float* p = &g_part[((size_t)(b * KG + kg) * CHUNKS + c) * (KPT * NSTAT) + j * NSTAT];
#pragma unroll
        for (int i = 0; i < NSTAT; i++) s[i] += p[i];
    }

    const float SP = s[0];
    const float rd = 1.0f / (1e-5f + SP);
    const float mu0 = s[1] * rd, mu1 = s[2] * rd, mu2 = s[3] * rd;

    const float c00 = (s[4] - 2.0f * mu0 * s[1] + SP * mu0 * mu0) * rd + 1e-3f;
    const float c01 = (s[5] - mu0 * s[2] - mu1 * s[1] + SP * mu0 * mu1) * rd;
    const float c02 = (s[6] - mu0 * s[3] - mu2 * s[1] + SP * mu0 * mu2) * rd;
    const float c11 = (s[7] - 2.0f * mu1 * s[2] + SP * mu1 * mu1) * rd + 1e-3f;
    const float c12 = (s[8] - mu1 * s[3] - mu2 * s[2] + SP * mu1 * mu2) * rd;
    const float c22 = (s[9] - 2.0f * mu2 * s[3] + SP * mu2 * mu2) * rd + 1e-3f;

    const float m00 = c11 * c22 - c12 * c12;
    const float m01 = c02 * c12 - c01 * c22;
    const float m02 = c01 * c12 - c02 * c11;
    const float det = c00 * m00 + c01 * m01 + c02 * m02;
    const float inv = 1.0f / det;

    const float i00 = m00 * inv;
    const float i01 = m01 * inv;
    const float i02 = m02 * inv;
    const float i11 = (c00 * c22 - c02 * c02) * inv;
    const float i12 = (c01 * c02 - c00 * c12) * inv;
    const float i22 = (c00 * c11 - c01 * c01) * inv;

    const float alpha = SP * (1.0f / (float)HW);
    const float logcoef = logf(alpha) - 0.5f * (3.0f * LOG_2PI + logf(det));

    // affine expansion: quad(x-mu) = Pq(x) - g.x + Pq(mu)
    const float g0 = i00 * mu0 + i01 * mu1 + i02 * mu2;
    const float g1 = i01 * mu0 + i11 * mu1 + i12 * mu2;
    const float g2 = i02 * mu0 + i12 * mu1 + i22 * mu2;
    const float Pmu = 0.5f * (i00 * mu0 * mu0 + i11 * mu1 * mu1 + i22 * mu2 * mu2)
                    + i01 * mu0 * mu1 + i02 * mu0 * mu2 + i12 * mu1 * mu2;

    float* out = &g_params[(size_t)(b * KN + k) * NSTAT];
    out[0] = (logcoef - Pmu) * LOG2E;
    out[1] = g0 * LOG2E;
    out[2] = g1 * LOG2E;
    out[3] = g2 * LOG2E;
    out[4] = -0.5f * i00 * LOG2E;
    out[5] = -0.5f * i11 * LOG2E;
    out[6] = -0.5f * i22 * LOG2E;
    out[7] = -i01 * LOG2E;
    out[8] = -i02 * LOG2E;
    out[9] = -i12 * LOG2E;
}

// ---------------------------------------------------------------------------
// Pass C: E-step, 2 pixels per thread (one f32x2 pair), single sweep.
// q[16] fits in 16 u64 regs -> low pressure, high occupancy, EX2 minimal.
// grid = (HW2/256, BN), block = 256
// ---------------------------------------------------------------------------
__global__ __launch_bounds__(256)
void gmm_estep_kernel(const float* __restrict__ I, float* __restrict__ out) {
    const int b = blockIdx.y;
    const int p = blockIdx.x * blockDim.x + threadIdx.x;

    __shared__ u64 spd[KN * NSTAT];   // params duplicated into both f32x2 lanes
    if (threadIdx.x < KN * NSTAT) {
        const float v = g_params[(size_t)b * KN * NSTAT + threadIdx.x];
        spd[threadIdx.x] = pack2(v, v);
    }
    __syncthreads();

    const float2 a0 = ((const float2*)(I + (size_t)(b * 3 + 0) * HW))[p];
    const float2 a1 = ((const float2*)(I + (size_t)(b * 3 + 1) * HW))[p];
    const float2 a2 = ((const float2*)(I + (size_t)(b * 3 + 2) * HW))[p];

    const u64 X0 = pack2(a0.x, a0.y);
    const u64 X1 = pack2(a1.x, a1.y);
    const u64 X2 = pack2(a2.x, a2.y);
    const u64 XX00 = mul2(X0, X0);
    const u64 XX01 = mul2(X0, X1);
    const u64 XX02 = mul2(X0, X2);
    const u64 XX11 = mul2(X1, X1);
    const u64 XX12 = mul2(X1, X2);
    const u64 XX22 = mul2(X2, X2);

    u64 q[KN];
    u64 sum = 0ull;
#pragma unroll
    for (int k = 0; k < KN; k++) {
        const u64* pr = &spd[k * NSTAT];
        u64 t = fma2(pr[1], X0, pr[0]);
        t = fma2(pr[2], X1, t);
        t = fma2(pr[3], X2, t);
        t = fma2(pr[4], XX00, t);
        t = fma2(pr[5], XX11, t);
        t = fma2(pr[6], XX22, t);
        t = fma2(pr[7], XX01, t);
        t = fma2(pr[8], XX02, t);
        t = fma2(pr[9], XX12, t);
        const u64 e = exp2_2(t);
        q[k] = e;
        sum = add2(sum, e);
    }

    float s0, s1;
    unpack2(sum, s0, s1);
    const u64 R = pack2(1.0f / (1e-5f + s0), 1.0f / (1e-5f + s1));

    float2* __restrict__ o2 = (float2*)(out + (size_t)b * KN * HW);
#pragma unroll
    for (int k = 0; k < KN; k++) {
        const u64 v = mul2(q[k], R);
        float2 f;
        unpack2(v, f.x, f.y);
        __stcs(&o2[(size_t)k * HW2 + p], f);
    }
}

extern "C" void kernel_launch(void* const* d_in, const int* in_sizes, int n_in,
                              void* d_out, int out_size) {
    const float* Pij = (const float*)d_in[0];
    const float* I   = (const float*)d_in[1];
    float* out = (float*)d_out;

    dim3 gA(CHUNKS, KG, BN);
    gmm_reduce_kernel<<<gA, RTHREADS>>>(Pij, I);
    gmm_params_kernel<<<1, 64>>>();
    dim3 gC(HW2 / 256, BN);
    gmm_estep_kernel<<<gC, 256>>>(I, out);
}